// round 3
// baseline (speedup 1.0000x reference)
#include <cuda_runtime.h>
#include <cstdint>
#include <math.h>

#define N_NODES 10000
#define E_EDGES 640000
#define DIM     128
#define HEADS   4

__device__ float g_qproj[N_NODES * DIM];
__device__ float g_num[N_NODES * DIM];
__device__ float g_den[N_NODES * HEADS];
__device__ int   g_cnt[N_NODES];
__device__ int   g_cur[N_NODES];
__device__ int   g_perm[E_EDGES];
__device__ int   g_is32;

__device__ __forceinline__ uint32_t f2tf(float f) {
    uint32_t u;
    asm("cvt.rna.tf32.f32 %0, %1;" : "=r"(u) : "f"(f));
    return u;
}

// dst of edge e, dispatching on detected dtype of edge_index
__device__ __forceinline__ int get_dst(const void* ei, int e) {
    if (g_is32) return ((const int*)ei)[e];
    return (int)((const long long*)ei)[e];
}

// detect int32 vs int64 edge_index: int64 entries (dst<10000) have zero high words.
__global__ void k_detect(const void* ei, int E) {
    __shared__ int s;
    int tid = threadIdx.x;
    if (tid == 0) s = 0;
    __syncthreads();
    if (tid < 256 && tid < E) {
        long long v = ((const long long*)ei)[tid];
        if ((v >> 32) != 0) atomicOr(&s, 1);
    }
    __syncthreads();
    if (tid == 0) g_is32 = s;
}

__global__ void k_zero() {
    int i = blockIdx.x * blockDim.x + threadIdx.x;
    int st = gridDim.x * blockDim.x;
    for (int j = i; j < N_NODES * DIM; j += st) g_num[j] = 0.f;
    for (int j = i; j < N_NODES * HEADS; j += st) g_den[j] = 0.f;
    for (int j = i; j < N_NODES; j += st) g_cnt[j] = 0;
}

// 32-row x 128-col GEMM: Y = X @ W + b (fp32 FMA; N=10000 side work)
__global__ __launch_bounds__(256) void k_qproj(const float* __restrict__ X,
                                               const float* __restrict__ W,
                                               const float* __restrict__ b, int n) {
    extern __shared__ float sq[];
    float* Ws = sq;
    float* As = sq + DIM * DIM;
    int tid = threadIdx.x;
    for (int i = tid; i < DIM * DIM; i += 256) Ws[i] = W[i];
    int row0 = blockIdx.x * 32;
    for (int i = tid; i < 32 * DIM; i += 256) {
        int r = i >> 7, c = i & 127;
        int gr = row0 + r;
        As[r * 132 + c] = (gr < n) ? X[gr * DIM + c] : 0.f;
    }
    __syncthreads();
    int cg = (tid & 31) * 4, rg = (tid >> 5) * 4;
    float acc[4][4] = {};
    #pragma unroll 8
    for (int d = 0; d < DIM; d++) {
        float4 w = *(float4*)&Ws[d * DIM + cg];
        float a0 = As[(rg + 0) * 132 + d];
        float a1 = As[(rg + 1) * 132 + d];
        float a2 = As[(rg + 2) * 132 + d];
        float a3 = As[(rg + 3) * 132 + d];
        acc[0][0] += a0 * w.x; acc[0][1] += a0 * w.y; acc[0][2] += a0 * w.z; acc[0][3] += a0 * w.w;
        acc[1][0] += a1 * w.x; acc[1][1] += a1 * w.y; acc[1][2] += a1 * w.z; acc[1][3] += a1 * w.w;
        acc[2][0] += a2 * w.x; acc[2][1] += a2 * w.y; acc[2][2] += a2 * w.z; acc[2][3] += a2 * w.w;
        acc[3][0] += a3 * w.x; acc[3][1] += a3 * w.y; acc[3][2] += a3 * w.z; acc[3][3] += a3 * w.w;
    }
    float4 bb = *(const float4*)&b[cg];
    for (int rr = 0; rr < 4; rr++) {
        int gr = row0 + rg + rr;
        if (gr < n) {
            float4 o = make_float4(acc[rr][0] + bb.x, acc[rr][1] + bb.y,
                                   acc[rr][2] + bb.z, acc[rr][3] + bb.w);
            *(float4*)&g_qproj[gr * DIM + cg] = o;
        }
    }
}

__global__ void k_hist(const void* __restrict__ ei, int E) {
    int e = blockIdx.x * blockDim.x + threadIdx.x;
    if (e < E) atomicAdd(&g_cnt[get_dst(ei, e)], 1);
}

__global__ void k_scan(int n) {
    __shared__ int sc[1024];
    int t = threadIdx.x;
    int carry = 0;
    for (int base = 0; base < n; base += 1024) {
        int idx = base + t;
        int v = (idx < n) ? g_cnt[idx] : 0;
        sc[t] = v;
        __syncthreads();
        int x = v;
        for (int off = 1; off < 1024; off <<= 1) {
            int y = (t >= off) ? sc[t - off] : 0;
            __syncthreads();
            x += y;
            sc[t] = x;
            __syncthreads();
        }
        if (idx < n) g_cur[idx] = carry + x - v;
        int tot = sc[1023];
        __syncthreads();
        carry += tot;
    }
}

__global__ void k_scatter(const void* __restrict__ ei, int E) {
    int e = blockIdx.x * blockDim.x + threadIdx.x;
    if (e < E) {
        int pos = atomicAdd(&g_cur[get_dst(ei, e)], 1);
        g_perm[pos] = e;
    }
}

// smem layout (bytes)
#define WS_OFF_B   0
#define BUF_OFF_B  66560
#define EXS_OFF_B  134144
#define BIAS_OFF_B 136192
#define DST_OFF_B  136704
#define PES_OFF_B  137216
#define SMEM_MAIN  137728

__device__ __forceinline__ void load_W_s(uint2* Ws, float* biass,
                                         const float* __restrict__ W,
                                         const float* __restrict__ b, int tid) {
    for (int i = tid; i < 64 * DIM; i += 256) {
        int kp = i >> 7, n = i & 127;
        int k1 = (kp >> 2) * 8 + (kp & 3);
        Ws[n * 65 + kp] = make_uint2(f2tf(W[k1 * DIM + n]), f2tf(W[(k1 + 4) * DIM + n]));
    }
    if (tid < DIM) biass[tid] = b[tid];
}

__device__ __forceinline__ void load_tile_s(uint32_t* AiU, const float* __restrict__ src,
                                            const int* pes, int w, int lane) {
    for (int r = w * 16; r < w * 16 + 16; r++) {
        const float4* row = (const float4*)(src + (size_t)pes[r] * DIM);
        float4 v = __ldg(&row[lane]);
        float vv[4] = {v.x, v.y, v.z, v.w};
        int base = r * 130;
        #pragma unroll
        for (int j = 0; j < 4; j++) {
            int kj = 4 * lane + j;
            int ks = kj >> 3, rr = kj & 7;
            int fidx = ((ks * 4 + (rr & 3)) << 1) | (rr >> 2);
            AiU[base + fidx] = f2tf(vv[j]);
        }
    }
}

__device__ __forceinline__ void gemm_tile(const uint2* __restrict__ A,
                                          const uint2* __restrict__ Wm,
                                          float acc[16][4], int m0, int g, int tg) {
    #pragma unroll 4
    for (int ks = 0; ks < 16; ks++) {
        int kk = ks * 4 + tg;
        uint2 pa = A[(m0 + g) * 65 + kk];
        uint2 pb = A[(m0 + g + 8) * 65 + kk];
        #pragma unroll
        for (int nb = 0; nb < 16; nb++) {
            uint2 wb = Wm[(8 * nb + g) * 65 + kk];
            asm volatile(
                "mma.sync.aligned.m16n8k8.row.col.f32.tf32.tf32.f32 "
                "{%0,%1,%2,%3},{%4,%5,%6,%7},{%8,%9},{%0,%1,%2,%3};"
                : "+f"(acc[nb][0]), "+f"(acc[nb][1]), "+f"(acc[nb][2]), "+f"(acc[nb][3])
                : "r"(pa.x), "r"(pb.x), "r"(pa.y), "r"(pb.y), "r"(wb.x), "r"(wb.y));
        }
    }
}

__global__ __launch_bounds__(256, 1) void k_main(const float* __restrict__ ke,
                                                 const float* __restrict__ ve,
                                                 const float* __restrict__ Wk,
                                                 const float* __restrict__ bk,
                                                 const float* __restrict__ Wv,
                                                 const float* __restrict__ bv,
                                                 const void* __restrict__ ei, int E) {
    extern __shared__ char smraw[];
    uint2*    Ws    = (uint2*)(smraw + WS_OFF_B);
    uint32_t* AiU   = (uint32_t*)(smraw + BUF_OFF_B);
    uint2*    Ai2   = (uint2*)(smraw + BUF_OFF_B);
    float*    Kp    = (float*)(smraw + BUF_OFF_B);
    float*    exs   = (float*)(smraw + EXS_OFF_B);
    float*    biass = (float*)(smraw + BIAS_OFF_B);
    int*      dsts  = (int*)(smraw + DST_OFF_B);
    int*      pess  = (int*)(smraw + PES_OFF_B);

    int tid = threadIdx.x, lane = tid & 31, w = tid >> 5;
    int g = lane >> 2, tg = lane & 3;
    int tile0 = blockIdx.x * 128;
    int m0 = w * 16;

    if (tid < 128) {
        int gi = tile0 + tid;
        int pe = (gi < E) ? g_perm[gi] : g_perm[E - 1];
        pess[tid] = pe;
        dsts[tid] = get_dst(ei, pe);
    }
    load_W_s(Ws, biass, Wk, bk, tid);
    __syncthreads();

    load_tile_s(AiU, ke, pess, w, lane);
    __syncthreads();

    float acc[16][4];
    #pragma unroll
    for (int i = 0; i < 16; i++) acc[i][0] = acc[i][1] = acc[i][2] = acc[i][3] = 0.f;
    gemm_tile(Ai2, Ws, acc, m0, g, tg);
    __syncthreads();

    #pragma unroll
    for (int nb = 0; nb < 16; nb++) {
        int col = 8 * nb + 2 * tg;
        float b0 = biass[col], b1 = biass[col + 1];
        *(float2*)&Kp[(m0 + g) * 132 + col]     = make_float2(acc[nb][0] + b0, acc[nb][1] + b1);
        *(float2*)&Kp[(m0 + g + 8) * 132 + col] = make_float2(acc[nb][2] + b0, acc[nb][3] + b1);
    }
    __syncthreads();

    const float scale = 0.17677669529663689f;  // 1/sqrt(32)
    for (int i = m0; i < m0 + 16; i++) {
        int nd = dsts[i];
        float4 qv = __ldg((const float4*)&g_qproj[nd * DIM + lane * 4]);
        float4 kv = *(float4*)&Kp[i * 132 + lane * 4];
        float p = qv.x * kv.x + qv.y * kv.y + qv.z * kv.z + qv.w * kv.w;
        p += __shfl_xor_sync(0xffffffffu, p, 1);
        p += __shfl_xor_sync(0xffffffffu, p, 2);
        p += __shfl_xor_sync(0xffffffffu, p, 4);
        float ex = ((tile0 + i) < E) ? __expf(p * scale) : 0.f;
        if ((lane & 7) == 0) exs[i * HEADS + (lane >> 3)] = ex;
    }
    __syncthreads();

    load_W_s(Ws, biass, Wv, bv, tid);
    load_tile_s(AiU, ve, pess, w, lane);
    __syncthreads();

    #pragma unroll
    for (int i = 0; i < 16; i++) acc[i][0] = acc[i][1] = acc[i][2] = acc[i][3] = 0.f;
    gemm_tile(Ai2, Ws, acc, m0, g, tg);
    __syncthreads();

    float ex0[HEADS], ex1[HEADS];
    #pragma unroll
    for (int h = 0; h < HEADS; h++) {
        ex0[h] = exs[(m0 + g) * HEADS + h];
        ex1[h] = exs[(m0 + g + 8) * HEADS + h];
    }
    #pragma unroll
    for (int nb = 0; nb < 16; nb++) {
        int col = 8 * nb + 2 * tg;
        int h = nb >> 2;
        float b0 = biass[col], b1 = biass[col + 1];
        *(float2*)&Kp[(m0 + g) * 132 + col] =
            make_float2((acc[nb][0] + b0) * ex0[h], (acc[nb][1] + b1) * ex0[h]);
        *(float2*)&Kp[(m0 + g + 8) * 132 + col] =
            make_float2((acc[nb][2] + b0) * ex1[h], (acc[nb][3] + b1) * ex1[h]);
    }
    __syncthreads();

    if (tid < 128) {
        float a = 0.f;
        for (int r = 0; r < 128; r++) {
            a += Kp[r * 132 + tid];
            if (r == 127 || dsts[r + 1] != dsts[r]) {
                atomicAdd(&g_num[dsts[r] * DIM + tid], a);
                a = 0.f;
            }
        }
    } else if (tid < 128 + HEADS) {
        int h = tid - 128;
        float a = 0.f;
        for (int r = 0; r < 128; r++) {
            a += exs[r * HEADS + h];
            if (r == 127 || dsts[r + 1] != dsts[r]) {
                atomicAdd(&g_den[dsts[r] * HEADS + h], a);
                a = 0.f;
            }
        }
    }
}

__global__ __launch_bounds__(256) void k_out(const float* __restrict__ W,
                                             const float* __restrict__ b,
                                             float* __restrict__ Y, int n) {
    extern __shared__ float so[];
    float* Ws = so;
    float* As = so + DIM * DIM;
    int tid = threadIdx.x;
    for (int i = tid; i < DIM * DIM; i += 256) Ws[i] = W[i];
    int row0 = blockIdx.x * 32;
    for (int i = tid; i < 32 * DIM; i += 256) {
        int r = i >> 7, c = i & 127;
        int gr = row0 + r;
        float v = 0.f;
        if (gr < n) {
            float den = g_den[gr * HEADS + (c >> 5)];
            v = (den > 0.f) ? g_num[gr * DIM + c] / den : 0.f;
        }
        As[r * 132 + c] = v;
    }
    __syncthreads();
    int cg = (tid & 31) * 4, rg = (tid >> 5) * 4;
    float acc[4][4] = {};
    #pragma unroll 8
    for (int d = 0; d < DIM; d++) {
        float4 w = *(float4*)&Ws[d * DIM + cg];
        float a0 = As[(rg + 0) * 132 + d];
        float a1 = As[(rg + 1) * 132 + d];
        float a2 = As[(rg + 2) * 132 + d];
        float a3 = As[(rg + 3) * 132 + d];
        acc[0][0] += a0 * w.x; acc[0][1] += a0 * w.y; acc[0][2] += a0 * w.z; acc[0][3] += a0 * w.w;
        acc[1][0] += a1 * w.x; acc[1][1] += a1 * w.y; acc[1][2] += a1 * w.z; acc[1][3] += a1 * w.w;
        acc[2][0] += a2 * w.x; acc[2][1] += a2 * w.y; acc[2][2] += a2 * w.z; acc[2][3] += a2 * w.w;
        acc[3][0] += a3 * w.x; acc[3][1] += a3 * w.y; acc[3][2] += a3 * w.z; acc[3][3] += a3 * w.w;
    }
    float4 bb = *(const float4*)&b[cg];
    for (int rr = 0; rr < 4; rr++) {
        int gr = row0 + rg + rr;
        if (gr < n) {
            float4 o = make_float4(acc[rr][0] + bb.x, acc[rr][1] + bb.y,
                                   acc[rr][2] + bb.z, acc[rr][3] + bb.w);
            *(float4*)&Y[gr * DIM + cg] = o;
        }
    }
}

extern "C" void kernel_launch(void* const* d_in, const int* in_sizes, int n_in,
                              void* d_out, int out_size) {
    const float* q_nodes = (const float*)d_in[0];
    const float* k_edges = (const float*)d_in[1];
    const float* v_edges = (const float*)d_in[2];
    const float* Wq = (const float*)d_in[3];
    const float* bq = (const float*)d_in[4];
    const float* Wk = (const float*)d_in[5];
    const float* bk = (const float*)d_in[6];
    const float* Wv = (const float*)d_in[7];
    const float* bv = (const float*)d_in[8];
    const float* Wo = (const float*)d_in[9];
    const float* bo = (const float*)d_in[10];
    const void*  ei = (const void*)d_in[11];

    int N = in_sizes[0] / DIM;
    int E = in_sizes[1] / DIM;

    const int smem_small = (DIM * DIM + 32 * 132) * (int)sizeof(float);
    cudaFuncSetAttribute(k_qproj, cudaFuncAttributeMaxDynamicSharedMemorySize, smem_small);
    cudaFuncSetAttribute(k_out, cudaFuncAttributeMaxDynamicSharedMemorySize, smem_small);
    cudaFuncSetAttribute(k_main, cudaFuncAttributeMaxDynamicSharedMemorySize, SMEM_MAIN);

    k_detect<<<1, 256>>>(ei, E);
    k_zero<<<256, 256>>>();
    k_qproj<<<(N + 31) / 32, 256, smem_small>>>(q_nodes, Wq, bq, N);
    k_hist<<<(E + 255) / 256, 256>>>(ei, E);
    k_scan<<<1, 1024>>>(N);
    k_scatter<<<(E + 255) / 256, 256>>>(ei, E);
    k_main<<<(E + 127) / 128, 256, SMEM_MAIN>>>(k_edges, v_edges, Wk, bk, Wv, bv, ei, E);
    k_out<<<(N + 31) / 32, 256, smem_small>>>(Wo, bo, (float*)d_out, N);
}

// round 4
// speedup vs baseline: 1.4028x; 1.4028x over previous
#include <cuda_runtime.h>
#include <cstdint>
#include <math.h>

#define N_NODES 10000
#define E_EDGES 640000
#define DIM     128
#define HEADS   4

__device__ float g_qproj[N_NODES * DIM];
__device__ float g_num[N_NODES * DIM];
__device__ float g_den[N_NODES * HEADS];
__device__ float g_ex[E_EDGES * HEADS];
__device__ int   g_cnt[N_NODES];
__device__ int   g_cur[N_NODES];
__device__ int   g_perm[E_EDGES];
__device__ int   g_is32;

__device__ __forceinline__ uint32_t f2tf(float f) {
    uint32_t u;
    asm("cvt.rna.tf32.f32 %0, %1;" : "=r"(u) : "f"(f));
    return u;
}

__device__ __forceinline__ int get_dst(const void* ei, int e) {
    if (g_is32) return ((const int*)ei)[e];
    return (int)((const long long*)ei)[e];
}

__device__ __forceinline__ void cp16(uint32_t sdst, const void* gsrc) {
    asm volatile("cp.async.cg.shared.global [%0], [%1], 16;" :: "r"(sdst), "l"(gsrc));
}

// zero scratch + detect edge_index dtype (int32 vs int64)
__global__ void k_zero_detect(const void* ei, int E) {
    int i = blockIdx.x * blockDim.x + threadIdx.x;
    int st = gridDim.x * blockDim.x;
    for (int j = i; j < N_NODES * DIM; j += st) g_num[j] = 0.f;
    for (int j = i; j < N_NODES * HEADS; j += st) g_den[j] = 0.f;
    for (int j = i; j < N_NODES; j += st) g_cnt[j] = 0;
    if (blockIdx.x == 0) {
        __shared__ int s;
        if (threadIdx.x == 0) s = 0;
        __syncthreads();
        if (threadIdx.x < 256 && threadIdx.x < E) {
            long long v = ((const long long*)ei)[threadIdx.x];
            if ((v >> 32) != 0) atomicOr(&s, 1);
        }
        __syncthreads();
        if (threadIdx.x == 0) g_is32 = s;
    }
}

__global__ __launch_bounds__(256) void k_qproj(const float* __restrict__ X,
                                               const float* __restrict__ W,
                                               const float* __restrict__ b, int n) {
    extern __shared__ float sq[];
    float* Ws = sq;
    float* As = sq + DIM * DIM;
    int tid = threadIdx.x;
    for (int i = tid; i < DIM * DIM; i += 256) Ws[i] = W[i];
    int row0 = blockIdx.x * 32;
    for (int i = tid; i < 32 * DIM; i += 256) {
        int r = i >> 7, c = i & 127;
        int gr = row0 + r;
        As[r * 132 + c] = (gr < n) ? X[gr * DIM + c] : 0.f;
    }
    __syncthreads();
    int cg = (tid & 31) * 4, rg = (tid >> 5) * 4;
    float acc[4][4] = {};
    #pragma unroll 8
    for (int d = 0; d < DIM; d++) {
        float4 w = *(float4*)&Ws[d * DIM + cg];
        float a0 = As[(rg + 0) * 132 + d];
        float a1 = As[(rg + 1) * 132 + d];
        float a2 = As[(rg + 2) * 132 + d];
        float a3 = As[(rg + 3) * 132 + d];
        acc[0][0] += a0 * w.x; acc[0][1] += a0 * w.y; acc[0][2] += a0 * w.z; acc[0][3] += a0 * w.w;
        acc[1][0] += a1 * w.x; acc[1][1] += a1 * w.y; acc[1][2] += a1 * w.z; acc[1][3] += a1 * w.w;
        acc[2][0] += a2 * w.x; acc[2][1] += a2 * w.y; acc[2][2] += a2 * w.z; acc[2][3] += a2 * w.w;
        acc[3][0] += a3 * w.x; acc[3][1] += a3 * w.y; acc[3][2] += a3 * w.z; acc[3][3] += a3 * w.w;
    }
    float4 bb = *(const float4*)&b[cg];
    for (int rr = 0; rr < 4; rr++) {
        int gr = row0 + rg + rr;
        if (gr < n) {
            float4 o = make_float4(acc[rr][0] + bb.x, acc[rr][1] + bb.y,
                                   acc[rr][2] + bb.z, acc[rr][3] + bb.w);
            *(float4*)&g_qproj[gr * DIM + cg] = o;
        }
    }
}

__global__ void k_hist(const void* __restrict__ ei, int E) {
    int e = blockIdx.x * blockDim.x + threadIdx.x;
    if (e < E) atomicAdd(&g_cnt[get_dst(ei, e)], 1);
}

__global__ void k_scan(int n) {
    __shared__ int sc[1024];
    int t = threadIdx.x;
    int carry = 0;
    for (int base = 0; base < n; base += 1024) {
        int idx = base + t;
        int v = (idx < n) ? g_cnt[idx] : 0;
        sc[t] = v;
        __syncthreads();
        int x = v;
        for (int off = 1; off < 1024; off <<= 1) {
            int y = (t >= off) ? sc[t - off] : 0;
            __syncthreads();
            x += y;
            sc[t] = x;
            __syncthreads();
        }
        if (idx < n) g_cur[idx] = carry + x - v;
        int tot = sc[1023];
        __syncthreads();
        carry += tot;
    }
}

__global__ void k_scatter(const void* __restrict__ ei, int E) {
    int e = blockIdx.x * blockDim.x + threadIdx.x;
    if (e < E) {
        int pos = atomicAdd(&g_cur[get_dst(ei, e)], 1);
        g_perm[pos] = e;
    }
}

// ---- persistent main kernels: smem layout (bytes) ----
#define WS_B    0
#define BUF0_B  66560
#define BUF1_B  134144
#define SMEM_A  201728
#define DST0_B  201728
#define DST1_B  202240
#define SMEM_B  202752

__device__ __forceinline__ void load_W_smem(uint2* Ws, const float* __restrict__ W, int tid) {
    for (int i = tid; i < 64 * DIM; i += 256) {
        int kp = i >> 7, n = i & 127;
        int k1 = (kp >> 2) * 8 + (kp & 3);
        Ws[n * 65 + kp] = make_uint2(f2tf(W[k1 * DIM + n]), f2tf(W[(k1 + 4) * DIM + n]));
    }
}

// prefetch one 128-row tile of gathered rows into smem (raw fp32) via cp.async
__device__ __forceinline__ void prefetch_tile(char* sm, int buf_b, const float* __restrict__ src,
                                              int tile, int E, int tid) {
    int row = tid >> 1;
    int gi = tile * 128 + row;
    if (gi >= E) gi = E - 1;
    int pe = g_perm[gi];
    const char* gsrc = (const char*)(src + (size_t)pe * DIM) + (tid & 1) * 256;
    uint32_t sdst = (uint32_t)__cvta_generic_to_shared(sm + buf_b + row * 528 + (tid & 1) * 256);
    #pragma unroll
    for (int j = 0; j < 16; j++) cp16(sdst + j * 16, gsrc + j * 16);
}

__device__ __forceinline__ void gemm_raw(const float* __restrict__ bufA,
                                         const uint2* __restrict__ Ws,
                                         float acc[16][4], int m0, int g, int tg) {
    #pragma unroll
    for (int ks = 0; ks < 16; ks++) {
        int c0 = ks * 8 + tg;
        uint32_t a0 = f2tf(bufA[(m0 + g) * 132 + c0]);
        uint32_t a1 = f2tf(bufA[(m0 + g + 8) * 132 + c0]);
        uint32_t a2 = f2tf(bufA[(m0 + g) * 132 + c0 + 4]);
        uint32_t a3 = f2tf(bufA[(m0 + g + 8) * 132 + c0 + 4]);
        int kk = ks * 4 + tg;
        #pragma unroll
        for (int nb = 0; nb < 16; nb++) {
            uint2 wb = Ws[(8 * nb + g) * 65 + kk];
            asm volatile(
                "mma.sync.aligned.m16n8k8.row.col.f32.tf32.tf32.f32 "
                "{%0,%1,%2,%3},{%4,%5,%6,%7},{%8,%9},{%0,%1,%2,%3};"
                : "+f"(acc[nb][0]), "+f"(acc[nb][1]), "+f"(acc[nb][2]), "+f"(acc[nb][3])
                : "r"(a0), "r"(a1), "r"(a2), "r"(a3), "r"(wb.x), "r"(wb.y));
        }
    }
}

// kernel A: K projection + fragment-direct scores -> g_ex
__global__ __launch_bounds__(256, 1) void k_score(const float* __restrict__ ke,
                                                  const float* __restrict__ Wk,
                                                  const float* __restrict__ bk,
                                                  const void* __restrict__ ei,
                                                  int E, int ntiles) {
    extern __shared__ char sm[];
    uint2* Ws = (uint2*)(sm + WS_B);
    int tid = threadIdx.x, lane = tid & 31, w = tid >> 5;
    int g = lane >> 2, tg = lane & 3;
    int m0 = w * 16;
    int STRIDE = gridDim.x, bid = blockIdx.x;

    load_W_smem(Ws, Wk, tid);
    float2 bkf[16];
    #pragma unroll
    for (int nb = 0; nb < 16; nb++) bkf[nb] = *(const float2*)&bk[8 * nb + 2 * tg];

    if (bid < ntiles) prefetch_tile(sm, BUF0_B, ke, bid, E, tid);
    asm volatile("cp.async.commit_group;");

    int par = 0;
    for (int t = bid; t < ntiles; t += STRIDE, par ^= 1) {
        int nt = t + STRIDE;
        if (nt < ntiles) prefetch_tile(sm, par ? BUF0_B : BUF1_B, ke, nt, E, tid);
        asm volatile("cp.async.commit_group;");

        // dst chain for current tile (direct, redundant across tg lanes -> L1 bcast)
        int gi0 = t * 128 + m0 + g, gi1 = gi0 + 8;
        int cg0 = gi0 >= E ? E - 1 : gi0;
        int cg1 = gi1 >= E ? E - 1 : gi1;
        int nd0 = get_dst(ei, g_perm[cg0]);
        int nd1 = get_dst(ei, g_perm[cg1]);

        asm volatile("cp.async.wait_group 1;");
        __syncthreads();

        // q fragment prefetch (latency hidden behind gemm)
        float2 q0[16], q1[16];
        #pragma unroll
        for (int nb = 0; nb < 16; nb++) {
            q0[nb] = *(const float2*)&g_qproj[nd0 * DIM + 8 * nb + 2 * tg];
            q1[nb] = *(const float2*)&g_qproj[nd1 * DIM + 8 * nb + 2 * tg];
        }

        const float* bufA = (const float*)(sm + (par ? BUF1_B : BUF0_B));
        float acc[16][4];
        #pragma unroll
        for (int i = 0; i < 16; i++) acc[i][0] = acc[i][1] = acc[i][2] = acc[i][3] = 0.f;
        gemm_raw(bufA, Ws, acc, m0, g, tg);

        float p0[4] = {0.f, 0.f, 0.f, 0.f}, p1[4] = {0.f, 0.f, 0.f, 0.f};
        #pragma unroll
        for (int nb = 0; nb < 16; nb++) {
            int h = nb >> 2;
            p0[h] += (acc[nb][0] + bkf[nb].x) * q0[nb].x + (acc[nb][1] + bkf[nb].y) * q0[nb].y;
            p1[h] += (acc[nb][2] + bkf[nb].x) * q1[nb].x + (acc[nb][3] + bkf[nb].y) * q1[nb].y;
        }
        #pragma unroll
        for (int h = 0; h < 4; h++) {
            p0[h] += __shfl_xor_sync(0xffffffffu, p0[h], 1);
            p0[h] += __shfl_xor_sync(0xffffffffu, p0[h], 2);
            p1[h] += __shfl_xor_sync(0xffffffffu, p1[h], 1);
            p1[h] += __shfl_xor_sync(0xffffffffu, p1[h], 2);
        }
        float s0 = tg == 0 ? p0[0] : tg == 1 ? p0[1] : tg == 2 ? p0[2] : p0[3];
        float s1 = tg == 0 ? p1[0] : tg == 1 ? p1[1] : tg == 2 ? p1[2] : p1[3];
        const float scale = 0.17677669529663689f;  // 1/sqrt(32)
        if (gi0 < E) g_ex[(size_t)gi0 * 4 + tg] = __expf(s0 * scale);
        if (gi1 < E) g_ex[(size_t)gi1 * 4 + tg] = __expf(s1 * scale);
        __syncthreads();
    }
}

// kernel B: V projection * ex + segmented reduce -> g_num/g_den
__global__ __launch_bounds__(256, 1) void k_aggr(const float* __restrict__ ve,
                                                 const float* __restrict__ Wv,
                                                 const float* __restrict__ bv,
                                                 const void* __restrict__ ei,
                                                 int E, int ntiles) {
    extern __shared__ char sm[];
    uint2* Ws = (uint2*)(sm + WS_B);
    int* dtab[2] = {(int*)(sm + DST0_B), (int*)(sm + DST1_B)};
    int tid = threadIdx.x, lane = tid & 31, w = tid >> 5;
    int g = lane >> 2, tg = lane & 3;
    int m0 = w * 16;
    int STRIDE = gridDim.x, bid = blockIdx.x;

    load_W_smem(Ws, Wv, tid);
    float2 bvf[16];
    #pragma unroll
    for (int nb = 0; nb < 16; nb++) bvf[nb] = *(const float2*)&bv[8 * nb + 2 * tg];

    if (bid < ntiles) {
        prefetch_tile(sm, BUF0_B, ve, bid, E, tid);
        if (tid < 128) {
            int gi = bid * 128 + tid;
            if (gi >= E) gi = E - 1;
            dtab[0][tid] = get_dst(ei, g_perm[gi]);
        }
    }
    asm volatile("cp.async.commit_group;");
    __syncthreads();

    int par = 0;
    for (int t = bid; t < ntiles; t += STRIDE, par ^= 1) {
        int nt = t + STRIDE;
        if (nt < ntiles) {
            prefetch_tile(sm, par ? BUF0_B : BUF1_B, ve, nt, E, tid);
            if (tid < 128) {
                int gi = nt * 128 + tid;
                if (gi >= E) gi = E - 1;
                dtab[par ^ 1][tid] = get_dst(ei, g_perm[gi]);
            }
        }
        asm volatile("cp.async.commit_group;");

        int gi0 = t * 128 + m0 + g, gi1 = gi0 + 8;
        float4 exa = (gi0 < E) ? *(const float4*)&g_ex[(size_t)gi0 * 4] : make_float4(0.f, 0.f, 0.f, 0.f);
        float4 exb = (gi1 < E) ? *(const float4*)&g_ex[(size_t)gi1 * 4] : make_float4(0.f, 0.f, 0.f, 0.f);

        asm volatile("cp.async.wait_group 1;");
        __syncthreads();

        float* bufA = (float*)(sm + (par ? BUF1_B : BUF0_B));
        float acc[16][4];
        #pragma unroll
        for (int i = 0; i < 16; i++) acc[i][0] = acc[i][1] = acc[i][2] = acc[i][3] = 0.f;
        gemm_raw(bufA, Ws, acc, m0, g, tg);

        float ea[4] = {exa.x, exa.y, exa.z, exa.w};
        float eb[4] = {exb.x, exb.y, exb.z, exb.w};
        // weighted writeback into current buffer (warp-local rows -> safe aliasing)
        #pragma unroll
        for (int nb = 0; nb < 16; nb++) {
            int h = nb >> 2;
            int col = 8 * nb + 2 * tg;
            *(float2*)&bufA[(m0 + g) * 132 + col] =
                make_float2((acc[nb][0] + bvf[nb].x) * ea[h], (acc[nb][1] + bvf[nb].y) * ea[h]);
            *(float2*)&bufA[(m0 + g + 8) * 132 + col] =
                make_float2((acc[nb][2] + bvf[nb].x) * eb[h], (acc[nb][3] + bvf[nb].y) * eb[h]);
        }
        __syncthreads();

        // segmented column reduction (edges sorted by dst), split 2 x 64 rows
        const int* dd = dtab[par];
        int c = tid & 127, half = tid >> 7;
        int r0 = half * 64, r1 = r0 + 64;
        float a = 0.f;
        for (int r = r0; r < r1; r++) {
            a += bufA[r * 132 + c];
            if (r == r1 - 1 || dd[r + 1] != dd[r]) {
                atomicAdd(&g_num[dd[r] * DIM + c], a);
                a = 0.f;
            }
        }
        if (tid < 8) {
            int h = tid & 3, hf = tid >> 2;
            int rr0 = hf * 64, rr1 = rr0 + 64;
            float aa = 0.f;
            for (int r = rr0; r < rr1; r++) {
                int gie = t * 128 + r;
                aa += (gie < E) ? g_ex[(size_t)gie * 4 + h] : 0.f;
                if (r == rr1 - 1 || dd[r + 1] != dd[r]) {
                    atomicAdd(&g_den[dd[r] * HEADS + h], aa);
                    aa = 0.f;
                }
            }
        }
        __syncthreads();
    }
}

__global__ __launch_bounds__(256) void k_out(const float* __restrict__ W,
                                             const float* __restrict__ b,
                                             float* __restrict__ Y, int n) {
    extern __shared__ float so[];
    float* Ws = so;
    float* As = so + DIM * DIM;
    int tid = threadIdx.x;
    for (int i = tid; i < DIM * DIM; i += 256) Ws[i] = W[i];
    int row0 = blockIdx.x * 32;
    for (int i = tid; i < 32 * DIM; i += 256) {
        int r = i >> 7, c = i & 127;
        int gr = row0 + r;
        float v = 0.f;
        if (gr < n) {
            float den = g_den[gr * HEADS + (c >> 5)];
            v = (den > 0.f) ? g_num[gr * DIM + c] / den : 0.f;
        }
        As[r * 132 + c] = v;
    }
    __syncthreads();
    int cg = (tid & 31) * 4, rg = (tid >> 5) * 4;
    float acc[4][4] = {};
    #pragma unroll 8
    for (int d = 0; d < DIM; d++) {
        float4 w = *(float4*)&Ws[d * DIM + cg];
        float a0 = As[(rg + 0) * 132 + d];
        float a1 = As[(rg + 1) * 132 + d];
        float a2 = As[(rg + 2) * 132 + d];
        float a3 = As[(rg + 3) * 132 + d];
        acc[0][0] += a0 * w.x; acc[0][1] += a0 * w.y; acc[0][2] += a0 * w.z; acc[0][3] += a0 * w.w;
        acc[1][0] += a1 * w.x; acc[1][1] += a1 * w.y; acc[1][2] += a1 * w.z; acc[1][3] += a1 * w.w;
        acc[2][0] += a2 * w.x; acc[2][1] += a2 * w.y; acc[2][2] += a2 * w.z; acc[2][3] += a2 * w.w;
        acc[3][0] += a3 * w.x; acc[3][1] += a3 * w.y; acc[3][2] += a3 * w.z; acc[3][3] += a3 * w.w;
    }
    float4 bb = *(const float4*)&b[cg];
    for (int rr = 0; rr < 4; rr++) {
        int gr = row0 + rg + rr;
        if (gr < n) {
            float4 o = make_float4(acc[rr][0] + bb.x, acc[rr][1] + bb.y,
                                   acc[rr][2] + bb.z, acc[rr][3] + bb.w);
            *(float4*)&Y[gr * DIM + cg] = o;
        }
    }
}

extern "C" void kernel_launch(void* const* d_in, const int* in_sizes, int n_in,
                              void* d_out, int out_size) {
    const float* q_nodes = (const float*)d_in[0];
    const float* k_edges = (const float*)d_in[1];
    const float* v_edges = (const float*)d_in[2];
    const float* Wq = (const float*)d_in[3];
    const float* bq = (const float*)d_in[4];
    const float* Wk = (const float*)d_in[5];
    const float* bk = (const float*)d_in[6];
    const float* Wv = (const float*)d_in[7];
    const float* bv = (const float*)d_in[8];
    const float* Wo = (const float*)d_in[9];
    const float* bo = (const float*)d_in[10];
    const void*  ei = (const void*)d_in[11];

    int N = in_sizes[0] / DIM;
    int E = in_sizes[1] / DIM;
    int ntiles = (E + 127) / 128;

    int dev = 0, sms = 148;
    cudaGetDevice(&dev);
    cudaDeviceGetAttribute(&sms, cudaDevAttrMultiProcessorCount, dev);

    const int smem_small = (DIM * DIM + 32 * 132) * (int)sizeof(float);
    cudaFuncSetAttribute(k_qproj, cudaFuncAttributeMaxDynamicSharedMemorySize, smem_small);
    cudaFuncSetAttribute(k_out, cudaFuncAttributeMaxDynamicSharedMemorySize, smem_small);
    cudaFuncSetAttribute(k_score, cudaFuncAttributeMaxDynamicSharedMemorySize, SMEM_A);
    cudaFuncSetAttribute(k_aggr, cudaFuncAttributeMaxDynamicSharedMemorySize, SMEM_B);

    k_zero_detect<<<256, 256>>>(ei, E);
    k_qproj<<<(N + 31) / 32, 256, smem_small>>>(q_nodes, Wq, bq, N);
    k_hist<<<(E + 255) / 256, 256>>>(ei, E);
    k_scan<<<1, 1024>>>(N);
    k_scatter<<<(E + 255) / 256, 256>>>(ei, E);
    k_score<<<sms, 256, SMEM_A>>>(k_edges, Wk, bk, ei, E, ntiles);   // launch idx 5 -> profiled
    k_aggr<<<sms, 256, SMEM_B>>>(v_edges, Wv, bv, ei, E, ntiles);
    k_out<<<(N + 31) / 32, 256, smem_small>>>(Wo, bo, (float*)d_out, N);
}

// round 5
// speedup vs baseline: 1.8063x; 1.2876x over previous
#include <cuda_runtime.h>
#include <cstdint>
#include <math.h>

#define N_NODES 10000
#define E_EDGES 640000
#define DIM     128
#define HEADS   4

__device__ float g_qproj[N_NODES * DIM];
__device__ float g_num[N_NODES * DIM];
__device__ float g_den[N_NODES * HEADS];
__device__ float g_ex[E_EDGES * HEADS];
__device__ int   g_cnt[N_NODES];
__device__ int   g_cur[N_NODES];
__device__ int   g_perm[E_EDGES];
__device__ int   g_is32;

__device__ __forceinline__ uint32_t f2tf(float f) {
    uint32_t u;
    asm("cvt.rna.tf32.f32 %0, %1;" : "=r"(u) : "f"(f));
    return u;
}

__device__ __forceinline__ int get_dst(const void* ei, int e) {
    if (g_is32) return ((const int*)ei)[e];
    return (int)((const long long*)ei)[e];
}

__device__ __forceinline__ void cp16(uint32_t sdst, const void* gsrc) {
    asm volatile("cp.async.cg.shared.global [%0], [%1], 16;" :: "r"(sdst), "l"(gsrc));
}

// ---------------- setup kernels ----------------
__global__ void k_zero_detect(const void* ei, int E) {
    int i = blockIdx.x * blockDim.x + threadIdx.x;
    int st = gridDim.x * blockDim.x;
    for (int j = i; j < N_NODES * DIM; j += st) g_num[j] = 0.f;
    for (int j = i; j < N_NODES * HEADS; j += st) g_den[j] = 0.f;
    for (int j = i; j < N_NODES; j += st) g_cnt[j] = 0;
    if (blockIdx.x == 0) {
        __shared__ int s;
        if (threadIdx.x == 0) s = 0;
        __syncthreads();
        if (threadIdx.x < 256 && threadIdx.x < E) {
            long long v = ((const long long*)ei)[threadIdx.x];
            if ((v >> 32) != 0) atomicOr(&s, 1);
        }
        __syncthreads();
        if (threadIdx.x == 0) g_is32 = s;
    }
}

__global__ __launch_bounds__(256) void k_qproj(const float* __restrict__ X,
                                               const float* __restrict__ W,
                                               const float* __restrict__ b, int n) {
    extern __shared__ float sq[];
    float* Ws = sq;
    float* As = sq + DIM * DIM;
    int tid = threadIdx.x;
    for (int i = tid; i < DIM * DIM; i += 256) Ws[i] = W[i];
    int row0 = blockIdx.x * 32;
    for (int i = tid; i < 32 * DIM; i += 256) {
        int r = i >> 7, c = i & 127;
        int gr = row0 + r;
        As[r * 132 + c] = (gr < n) ? X[gr * DIM + c] : 0.f;
    }
    __syncthreads();
    int cg = (tid & 31) * 4, rg = (tid >> 5) * 4;
    float acc[4][4] = {};
    #pragma unroll 8
    for (int d = 0; d < DIM; d++) {
        float4 w = *(float4*)&Ws[d * DIM + cg];
        float a0 = As[(rg + 0) * 132 + d];
        float a1 = As[(rg + 1) * 132 + d];
        float a2 = As[(rg + 2) * 132 + d];
        float a3 = As[(rg + 3) * 132 + d];
        acc[0][0] += a0 * w.x; acc[0][1] += a0 * w.y; acc[0][2] += a0 * w.z; acc[0][3] += a0 * w.w;
        acc[1][0] += a1 * w.x; acc[1][1] += a1 * w.y; acc[1][2] += a1 * w.z; acc[1][3] += a1 * w.w;
        acc[2][0] += a2 * w.x; acc[2][1] += a2 * w.y; acc[2][2] += a2 * w.z; acc[2][3] += a2 * w.w;
        acc[3][0] += a3 * w.x; acc[3][1] += a3 * w.y; acc[3][2] += a3 * w.z; acc[3][3] += a3 * w.w;
    }
    float4 bb = *(const float4*)&b[cg];
    for (int rr = 0; rr < 4; rr++) {
        int gr = row0 + rg + rr;
        if (gr < n) {
            float4 o = make_float4(acc[rr][0] + bb.x, acc[rr][1] + bb.y,
                                   acc[rr][2] + bb.z, acc[rr][3] + bb.w);
            *(float4*)&g_qproj[gr * DIM + cg] = o;
        }
    }
}

__global__ void k_hist(const void* __restrict__ ei, int E) {
    int e = blockIdx.x * blockDim.x + threadIdx.x;
    if (e < E) atomicAdd(&g_cnt[get_dst(ei, e)], 1);
}

// shuffle-based single-block exclusive scan of g_cnt -> g_cur
__global__ __launch_bounds__(1024) void k_scan(int n) {
    __shared__ int ws[32];
    int t = threadIdx.x, lane = t & 31, wd = t >> 5;
    int per = (n + 1023) / 1024;
    int base = t * per;
    int s = 0;
    for (int i = 0; i < per; i++) {
        int idx = base + i;
        if (idx < n) s += g_cnt[idx];
    }
    int incl = s;
    #pragma unroll
    for (int off = 1; off < 32; off <<= 1) {
        int y = __shfl_up_sync(0xffffffffu, incl, off);
        if (lane >= off) incl += y;
    }
    if (lane == 31) ws[wd] = incl;
    __syncthreads();
    if (wd == 0) {
        int v = ws[lane];
        int iv = v;
        #pragma unroll
        for (int off = 1; off < 32; off <<= 1) {
            int y = __shfl_up_sync(0xffffffffu, iv, off);
            if (lane >= off) iv += y;
        }
        ws[lane] = iv - v;
    }
    __syncthreads();
    int run = ws[wd] + incl - s;
    for (int i = 0; i < per; i++) {
        int idx = base + i;
        if (idx < n) {
            int v = g_cnt[idx];
            g_cur[idx] = run;
            run += v;
        }
    }
}

__global__ void k_scatter(const void* __restrict__ ei, int E) {
    int e = blockIdx.x * blockDim.x + threadIdx.x;
    if (e < E) {
        int pos = atomicAdd(&g_cur[get_dst(ei, e)], 1);
        g_perm[pos] = e;
    }
}

// ---------------- persistent main kernels ----------------
// smem layout (bytes)
#define WSF_B   0        // 65536: fragment-contiguous tf32 weights
#define BUF0_B  65536    // 67584: tile 0 (128 rows x 132 floats)
#define BUF1_B  133120   // 67584: tile 1
#define SMEM_A  200704
#define PE0_B   200704
#define PE1_B   201216
#define DST0_B  201728
#define DST1_B  202240
#define SMEM_B  202752

// build fragment-contiguous weight smem: slot ((n>>3)*16 + (k>>3))*32 + 4*(n&7)+(k&3),
// uint2 component hi = (k>>2)&1 holds W[k, n] as tf32 (b-frag: {W[k1,n], W[k1+4,n]})
__device__ __forceinline__ void load_WsF(uint32_t* WsF, const float* __restrict__ W, int tid) {
    for (int i = tid; i < DIM * DIM; i += 256) {
        int k = i >> 7, n = i & 127;            // coalesced read of W[k*128+n]
        uint32_t v = f2tf(W[i]);
        int slot = ((n >> 3) * 16 + (k >> 3)) * 32 + 4 * (n & 7) + (k & 3);
        int hi = (k >> 2) & 1;
        WsF[slot * 2 + hi] = v;
    }
}

// prefetch one 128-row tile into smem (raw fp32); perm==nullptr -> natural order
__device__ __forceinline__ void prefetch_tile(char* sm, int buf_b, const float* __restrict__ src,
                                              const int* __restrict__ perm,
                                              int tile, int E, int tid) {
    int row = tid >> 1;
    int gi = tile * 128 + row;
    if (gi >= E) gi = E - 1;
    int pe = perm ? perm[gi] : gi;
    const char* gsrc = (const char*)(src + (size_t)pe * DIM) + (tid & 1) * 256;
    uint32_t sdst = (uint32_t)__cvta_generic_to_shared(sm + buf_b + row * 528 + (tid & 1) * 256);
    #pragma unroll
    for (int j = 0; j < 16; j++) cp16(sdst + j * 16, gsrc + j * 16);
}

// warp-tiled GEMM: warp (w>>1) -> m_base = 32*(w>>1); (w&1) -> n_base = 64*(w&1)
// acc[mi][nbi][4]: mi in 0..1 (m16 frags), nbi in 0..7 (n8 frags)
__device__ __forceinline__ void gemm_wtile(const float* __restrict__ buf,
                                           const uint2* __restrict__ WsF2,
                                           float acc[2][8][4], int m_base, int nb0,
                                           int g, int tg, int lane) {
    #pragma unroll
    for (int ks = 0; ks < 16; ks++) {
        int kc = ks * 8 + tg;
        uint32_t a[2][4];
        #pragma unroll
        for (int mi = 0; mi < 2; mi++) {
            int r = m_base + 16 * mi + g;
            a[mi][0] = f2tf(buf[r * 132 + kc]);
            a[mi][1] = f2tf(buf[(r + 8) * 132 + kc]);
            a[mi][2] = f2tf(buf[r * 132 + kc + 4]);
            a[mi][3] = f2tf(buf[(r + 8) * 132 + kc + 4]);
        }
        #pragma unroll
        for (int nbi = 0; nbi < 8; nbi++) {
            uint2 wb = WsF2[((nb0 + nbi) * 16 + ks) * 32 + lane];
            #pragma unroll
            for (int mi = 0; mi < 2; mi++) {
                asm volatile(
                    "mma.sync.aligned.m16n8k8.row.col.f32.tf32.tf32.f32 "
                    "{%0,%1,%2,%3},{%4,%5,%6,%7},{%8,%9},{%0,%1,%2,%3};"
                    : "+f"(acc[mi][nbi][0]), "+f"(acc[mi][nbi][1]),
                      "+f"(acc[mi][nbi][2]), "+f"(acc[mi][nbi][3])
                    : "r"(a[mi][0]), "r"(a[mi][1]), "r"(a[mi][2]), "r"(a[mi][3]),
                      "r"(wb.x), "r"(wb.y));
            }
        }
    }
}

// kernel A: K projection + fragment-direct scores -> g_ex (natural edge order)
__global__ __launch_bounds__(256, 1) void k_score(const float* __restrict__ ke,
                                                  const float* __restrict__ Wk,
                                                  const float* __restrict__ bk,
                                                  const void* __restrict__ ei,
                                                  int E, int ntiles) {
    extern __shared__ char sm[];
    uint32_t* WsF = (uint32_t*)(sm + WSF_B);
    const uint2* WsF2 = (const uint2*)(sm + WSF_B);
    int tid = threadIdx.x, lane = tid & 31, w = tid >> 5;
    int g = lane >> 2, tg = lane & 3;
    int m_base = (w >> 1) * 32, wn = w & 1, nb0 = wn * 8, n_base = wn * 64;
    int STRIDE = gridDim.x, bid = blockIdx.x;

    load_WsF(WsF, Wk, tid);
    float2 bkf[8];
    #pragma unroll
    for (int nbi = 0; nbi < 8; nbi++) bkf[nbi] = *(const float2*)&bk[n_base + 8 * nbi + 2 * tg];

    if (bid < ntiles) prefetch_tile(sm, BUF0_B, ke, nullptr, bid, E, tid);
    asm volatile("cp.async.commit_group;");
    __syncthreads();  // WsF ready

    int par = 0;
    const float scale = 0.17677669529663689f;  // 1/sqrt(32)
    for (int t = bid; t < ntiles; t += STRIDE, par ^= 1) {
        int nt = t + STRIDE;
        if (nt < ntiles) prefetch_tile(sm, par ? BUF0_B : BUF1_B, ke, nullptr, nt, E, tid);
        asm volatile("cp.async.commit_group;");

        int tile0 = t * 128;
        int e4[4], nd[4];
        #pragma unroll
        for (int j = 0; j < 4; j++) {
            e4[j] = tile0 + m_base + 16 * (j >> 1) + 8 * (j & 1) + g;
            int ce = e4[j] >= E ? E - 1 : e4[j];
            nd[j] = get_dst(ei, ce);
        }

        asm volatile("cp.async.wait_group 1;");
        __syncthreads();

        const float* buf = (const float*)(sm + (par ? BUF1_B : BUF0_B));
        float acc[2][8][4];
        #pragma unroll
        for (int mi = 0; mi < 2; mi++)
            #pragma unroll
            for (int nbi = 0; nbi < 8; nbi++)
                acc[mi][nbi][0] = acc[mi][nbi][1] = acc[mi][nbi][2] = acc[mi][nbi][3] = 0.f;
        gemm_wtile(buf, WsF2, acc, m_base, nb0, g, tg, lane);

        // fragment-direct scores: p[j][h'] = sum over this warp's 64 cols (2 heads)
        float p[4][2] = {{0.f, 0.f}, {0.f, 0.f}, {0.f, 0.f}, {0.f, 0.f}};
        #pragma unroll
        for (int nbi = 0; nbi < 8; nbi++) {
            int h = nbi >> 2;
            int col = n_base + 8 * nbi + 2 * tg;
            float2 bb = bkf[nbi];
            #pragma unroll
            for (int j = 0; j < 4; j++) {
                int mi = j >> 1, ai = (j & 1) * 2;
                float2 q = *(const float2*)&g_qproj[nd[j] * DIM + col];
                p[j][h] += (acc[mi][nbi][ai] + bb.x) * q.x + (acc[mi][nbi][ai + 1] + bb.y) * q.y;
            }
        }
        #pragma unroll
        for (int j = 0; j < 4; j++)
            #pragma unroll
            for (int h = 0; h < 2; h++) {
                p[j][h] += __shfl_xor_sync(0xffffffffu, p[j][h], 1);
                p[j][h] += __shfl_xor_sync(0xffffffffu, p[j][h], 2);
            }
        if (tg == 0) {
            #pragma unroll
            for (int j = 0; j < 4; j++)
                #pragma unroll
                for (int h = 0; h < 2; h++)
                    if (e4[j] < E)
                        g_ex[(size_t)e4[j] * 4 + wn * 2 + h] = __expf(p[j][h] * scale);
        }
        __syncthreads();  // all reads of buf done before it is re-prefetched
    }
}

// kernel B: V projection * ex + segmented reduce -> g_num/g_den (perm order)
__global__ __launch_bounds__(256, 1) void k_aggr(const float* __restrict__ ve,
                                                 const float* __restrict__ Wv,
                                                 const float* __restrict__ bv,
                                                 const void* __restrict__ ei,
                                                 int E, int ntiles) {
    extern __shared__ char sm[];
    uint32_t* WsF = (uint32_t*)(sm + WSF_B);
    const uint2* WsF2 = (const uint2*)(sm + WSF_B);
    int* petab[2] = {(int*)(sm + PE0_B), (int*)(sm + PE1_B)};
    int* dtab[2]  = {(int*)(sm + DST0_B), (int*)(sm + DST1_B)};
    int tid = threadIdx.x, lane = tid & 31, w = tid >> 5;
    int g = lane >> 2, tg = lane & 3;
    int m_base = (w >> 1) * 32, wn = w & 1, nb0 = wn * 8, n_base = wn * 64;
    int STRIDE = gridDim.x, bid = blockIdx.x;

    load_WsF(WsF, Wv, tid);
    float2 bvf[8];
    #pragma unroll
    for (int nbi = 0; nbi < 8; nbi++) bvf[nbi] = *(const float2*)&bv[n_base + 8 * nbi + 2 * tg];

    if (bid < ntiles) {
        prefetch_tile(sm, BUF0_B, ve, g_perm, bid, E, tid);
        if (tid < 128) {
            int gi = bid * 128 + tid;
            if (gi >= E) gi = E - 1;
            int pe = g_perm[gi];
            petab[0][tid] = pe;
            dtab[0][tid] = get_dst(ei, pe);
        }
    }
    asm volatile("cp.async.commit_group;");
    __syncthreads();

    int par = 0;
    for (int t = bid; t < ntiles; t += STRIDE, par ^= 1) {
        int nt = t + STRIDE;
        if (nt < ntiles) {
            prefetch_tile(sm, par ? BUF0_B : BUF1_B, ve, g_perm, nt, E, tid);
            if (tid < 128) {
                int gi = nt * 128 + tid;
                if (gi >= E) gi = E - 1;
                int pe = g_perm[gi];
                petab[par ^ 1][tid] = pe;
                dtab[par ^ 1][tid] = get_dst(ei, pe);
            }
        }
        asm volatile("cp.async.commit_group;");

        int tile0 = t * 128;
        const int* pet = petab[par];
        // ex for this warp's 2 heads, 4 rows
        int rj[4];
        float2 exv[4];
        #pragma unroll
        for (int j = 0; j < 4; j++) {
            rj[j] = m_base + 16 * (j >> 1) + 8 * (j & 1) + g;
            int gi = tile0 + rj[j];
            exv[j] = (gi < E) ? *(const float2*)&g_ex[(size_t)pet[rj[j]] * 4 + wn * 2]
                              : make_float2(0.f, 0.f);
        }

        asm volatile("cp.async.wait_group 1;");
        __syncthreads();

        float* buf = (float*)(sm + (par ? BUF1_B : BUF0_B));
        float acc[2][8][4];
        #pragma unroll
        for (int mi = 0; mi < 2; mi++)
            #pragma unroll
            for (int nbi = 0; nbi < 8; nbi++)
                acc[mi][nbi][0] = acc[mi][nbi][1] = acc[mi][nbi][2] = acc[mi][nbi][3] = 0.f;
        gemm_wtile(buf, WsF2, acc, m_base, nb0, g, tg, lane);
        __syncthreads();  // everyone done reading raw V rows before overwrite

        // weighted writeback into the current buffer
        #pragma unroll
        for (int nbi = 0; nbi < 8; nbi++) {
            int h = nbi >> 2;
            int col = n_base + 8 * nbi + 2 * tg;
            float2 bb = bvf[nbi];
            #pragma unroll
            for (int j = 0; j < 4; j++) {
                int mi = j >> 1, ai = (j & 1) * 2;
                float exj = h ? exv[j].y : exv[j].x;
                *(float2*)&buf[rj[j] * 132 + col] =
                    make_float2((acc[mi][nbi][ai] + bb.x) * exj,
                                (acc[mi][nbi][ai + 1] + bb.y) * exj);
            }
        }
        __syncthreads();

        // segmented column reduction (rows sorted by dst), split 2 x 64 rows
        const int* dd = dtab[par];
        int c = tid & 127, half = tid >> 7;
        int r0 = half * 64, r1 = r0 + 64;
        float a = 0.f;
        for (int r = r0; r < r1; r++) {
            a += buf[r * 132 + c];
            if (r == r1 - 1 || dd[r + 1] != dd[r]) {
                atomicAdd(&g_num[dd[r] * DIM + c], a);
                a = 0.f;
            }
        }
        if (tid < 8) {
            int h = tid & 3, hf = tid >> 2;
            int rr0 = hf * 64, rr1 = rr0 + 64;
            float aa = 0.f;
            for (int r = rr0; r < rr1; r++) {
                int gie = tile0 + r;
                aa += (gie < E) ? g_ex[(size_t)pet[r] * 4 + h] : 0.f;
                if (r == rr1 - 1 || dd[r + 1] != dd[r]) {
                    atomicAdd(&g_den[dd[r] * HEADS + h], aa);
                    aa = 0.f;
                }
            }
        }
        __syncthreads();
    }
}

__global__ __launch_bounds__(256) void k_out(const float* __restrict__ W,
                                             const float* __restrict__ b,
                                             float* __restrict__ Y, int n) {
    extern __shared__ float so[];
    float* Ws = so;
    float* As = so + DIM * DIM;
    int tid = threadIdx.x;
    for (int i = tid; i < DIM * DIM; i += 256) Ws[i] = W[i];
    int row0 = blockIdx.x * 32;
    for (int i = tid; i < 32 * DIM; i += 256) {
        int r = i >> 7, c = i & 127;
        int gr = row0 + r;
        float v = 0.f;
        if (gr < n) {
            float den = g_den[gr * HEADS + (c >> 5)];
            v = (den > 0.f) ? g_num[gr * DIM + c] / den : 0.f;
        }
        As[r * 132 + c] = v;
    }
    __syncthreads();
    int cg = (tid & 31) * 4, rg = (tid >> 5) * 4;
    float acc[4][4] = {};
    #pragma unroll 8
    for (int d = 0; d < DIM; d++) {
        float4 w = *(float4*)&Ws[d * DIM + cg];
        float a0 = As[(rg + 0) * 132 + d];
        float a1 = As[(rg + 1) * 132 + d];
        float a2 = As[(rg + 2) * 132 + d];
        float a3 = As[(rg + 3) * 132 + d];
        acc[0][0] += a0 * w.x; acc[0][1] += a0 * w.y; acc[0][2] += a0 * w.z; acc[0][3] += a0 * w.w;
        acc[1][0] += a1 * w.x; acc[1][1] += a1 * w.y; acc[1][2] += a1 * w.z; acc[1][3] += a1 * w.w;
        acc[2][0] += a2 * w.x; acc[2][1] += a2 * w.y; acc[2][2] += a2 * w.z; acc[2][3] += a2 * w.w;
        acc[3][0] += a3 * w.x; acc[3][1] += a3 * w.y; acc[3][2] += a3 * w.z; acc[3][3] += a3 * w.w;
    }
    float4 bb = *(const float4*)&b[cg];
    for (int rr = 0; rr < 4; rr++) {
        int gr = row0 + rg + rr;
        if (gr < n) {
            float4 o = make_float4(acc[rr][0] + bb.x, acc[rr][1] + bb.y,
                                   acc[rr][2] + bb.z, acc[rr][3] + bb.w);
            *(float4*)&Y[gr * DIM + cg] = o;
        }
    }
}

extern "C" void kernel_launch(void* const* d_in, const int* in_sizes, int n_in,
                              void* d_out, int out_size) {
    const float* q_nodes = (const float*)d_in[0];
    const float* k_edges = (const float*)d_in[1];
    const float* v_edges = (const float*)d_in[2];
    const float* Wq = (const float*)d_in[3];
    const float* bq = (const float*)d_in[4];
    const float* Wk = (const float*)d_in[5];
    const float* bk = (const float*)d_in[6];
    const float* Wv = (const float*)d_in[7];
    const float* bv = (const float*)d_in[8];
    const float* Wo = (const float*)d_in[9];
    const float* bo = (const float*)d_in[10];
    const void*  ei = (const void*)d_in[11];

    int N = in_sizes[0] / DIM;
    int E = in_sizes[1] / DIM;
    int ntiles = (E + 127) / 128;

    int dev = 0, sms = 148;
    cudaGetDevice(&dev);
    cudaDeviceGetAttribute(&sms, cudaDevAttrMultiProcessorCount, dev);

    const int smem_small = (DIM * DIM + 32 * 132) * (int)sizeof(float);
    cudaFuncSetAttribute(k_qproj, cudaFuncAttributeMaxDynamicSharedMemorySize, smem_small);
    cudaFuncSetAttribute(k_out, cudaFuncAttributeMaxDynamicSharedMemorySize, smem_small);
    cudaFuncSetAttribute(k_score, cudaFuncAttributeMaxDynamicSharedMemorySize, SMEM_A);
    cudaFuncSetAttribute(k_aggr, cudaFuncAttributeMaxDynamicSharedMemorySize, SMEM_B);

    // launch order chosen so k_score is launch idx 3 (the one ncu captures)
    k_zero_detect<<<256, 256>>>(ei, E);
    k_qproj<<<(N + 31) / 32, 256, smem_small>>>(q_nodes, Wq, bq, N);
    k_hist<<<(E + 255) / 256, 256>>>(ei, E);
    k_score<<<sms, 256, SMEM_A>>>(k_edges, Wk, bk, ei, E, ntiles);
    k_scan<<<1, 1024>>>(N);
    k_scatter<<<(E + 255) / 256, 256>>>(ei, E);
    k_aggr<<<sms, 256, SMEM_B>>>(v_edges, Wv, bv, ei, E, ntiles);
    k_out<<<(N + 31) / 32, 256, smem_small>>>(Wo, bo, (float*)d_out, N);
}

// round 6
// speedup vs baseline: 2.3306x; 1.2902x over previous
#include <cuda_runtime.h>
#include <cstdint>
#include <math.h>

#define N_NODES 10000
#define E_EDGES 640000
#define DIM     128
#define HEADS   4
#define TILE    64

__device__ float g_wt[N_NODES * 512];    // w-tilde [n][h][128], scale folded
__device__ float g_c[N_NODES * HEADS];   // score const per (n,h), scale folded
__device__ float g_S[N_NODES * 512];     // raw weighted v sums [n][h][128]
__device__ float g_agg[N_NODES * DIM];   // post-projection agg
__device__ float g_den[N_NODES * HEADS];
__device__ int   g_cnt[N_NODES];
__device__ int   g_cur[N_NODES];
__device__ int   g_perm[E_EDGES];
__device__ int   g_is32;

__device__ __forceinline__ int get_dst(const void* ei, int e) {
    if (g_is32) return ((const int*)ei)[e];
    return (int)((const long long*)ei)[e];
}

__device__ __forceinline__ void cp16(uint32_t sdst, const void* gsrc) {
    asm volatile("cp.async.cg.shared.global [%0], [%1], 16;" :: "r"(sdst), "l"(gsrc));
}

// ---------------- setup ----------------
__global__ void k_zero_detect(const void* ei, int E) {
    int i = blockIdx.x * blockDim.x + threadIdx.x;
    int st = gridDim.x * blockDim.x;
    for (int j = i; j < N_NODES * 512; j += st) g_S[j] = 0.f;
    for (int j = i; j < N_NODES * HEADS; j += st) g_den[j] = 0.f;
    for (int j = i; j < N_NODES; j += st) g_cnt[j] = 0;
    if (blockIdx.x == 0) {
        __shared__ int s;
        if (threadIdx.x == 0) s = 0;
        __syncthreads();
        if (threadIdx.x < 256 && threadIdx.x < E) {
            long long v = ((const long long*)ei)[threadIdx.x];
            if ((v >> 32) != 0) atomicOr(&s, 1);
        }
        __syncthreads();
        if (threadIdx.x == 0) g_is32 = s;
    }
}

// fused: q_proj (block-local) -> w_tilde + c  (per block: 32 nodes)
__global__ __launch_bounds__(256) void k_qw(const float* __restrict__ X,
                                            const float* __restrict__ Wq,
                                            const float* __restrict__ bq,
                                            const float* __restrict__ Wk,
                                            const float* __restrict__ bk, int n) {
    extern __shared__ float sw[];
    float* Ws = sw;                 // [128][132]
    float* As = sw + 128 * 132;     // [32][132]
    float* qs = As + 32 * 132;      // [32][132]
    int tid = threadIdx.x;
    int row0 = blockIdx.x * 32;

    for (int i = tid; i < DIM * DIM; i += 256) Ws[(i >> 7) * 132 + (i & 127)] = Wq[i];
    for (int i = tid; i < 32 * DIM; i += 256) {
        int r = i >> 7, c = i & 127;
        int gr = row0 + r;
        As[r * 132 + c] = (gr < n) ? X[gr * DIM + c] : 0.f;
    }
    __syncthreads();

    int cg = (tid & 31) * 4, rg = (tid >> 5) * 4;
    float acc[4][4] = {};
    #pragma unroll 8
    for (int d = 0; d < DIM; d++) {
        float4 w = *(float4*)&Ws[d * 132 + cg];
        float a0 = As[(rg + 0) * 132 + d];
        float a1 = As[(rg + 1) * 132 + d];
        float a2 = As[(rg + 2) * 132 + d];
        float a3 = As[(rg + 3) * 132 + d];
        acc[0][0] += a0 * w.x; acc[0][1] += a0 * w.y; acc[0][2] += a0 * w.z; acc[0][3] += a0 * w.w;
        acc[1][0] += a1 * w.x; acc[1][1] += a1 * w.y; acc[1][2] += a1 * w.z; acc[1][3] += a1 * w.w;
        acc[2][0] += a2 * w.x; acc[2][1] += a2 * w.y; acc[2][2] += a2 * w.z; acc[2][3] += a2 * w.w;
        acc[3][0] += a3 * w.x; acc[3][1] += a3 * w.y; acc[3][2] += a3 * w.z; acc[3][3] += a3 * w.w;
    }
    float4 bb = *(const float4*)&bq[cg];
    #pragma unroll
    for (int rr = 0; rr < 4; rr++) {
        qs[(rg + rr) * 132 + cg + 0] = acc[rr][0] + bb.x;
        qs[(rg + rr) * 132 + cg + 1] = acc[rr][1] + bb.y;
        qs[(rg + rr) * 132 + cg + 2] = acc[rr][2] + bb.z;
        qs[(rg + rr) * 132 + cg + 3] = acc[rr][3] + bb.w;
    }
    __syncthreads();

    for (int i = tid; i < DIM * DIM; i += 256) Ws[(i >> 7) * 132 + (i & 127)] = Wk[i];
    __syncthreads();

    const float scale = 0.17677669529663689f;  // 1/sqrt(32)
    int nl = tid >> 3, g = tid & 7;
    int node = row0 + nl;
    if (g < 4 && node < n) {
        int h = g;
        float cc = 0.f;
        #pragma unroll 8
        for (int d = 0; d < 32; d++) cc += qs[nl * 132 + h * 32 + d] * __ldg(&bk[h * 32 + d]);
        g_c[node * 4 + h] = cc * scale;
    }
    for (int kk = 0; kk < 16; kk++) {
        int k = kk * 8 + g;
        #pragma unroll
        for (int h = 0; h < 4; h++) {
            float acc2 = 0.f;
            #pragma unroll 8
            for (int d = 0; d < 32; d++)
                acc2 += Ws[k * 132 + h * 32 + d] * qs[nl * 132 + h * 32 + d];
            if (node < n) g_wt[node * 512 + h * 128 + k] = acc2 * scale;
        }
    }
}

__global__ void k_hist(const void* __restrict__ ei, int E) {
    int e = blockIdx.x * blockDim.x + threadIdx.x;
    if (e < E) atomicAdd(&g_cnt[get_dst(ei, e)], 1);
}

__global__ __launch_bounds__(1024) void k_scan(int n) {
    __shared__ int ws[32];
    int t = threadIdx.x, lane = t & 31, wd = t >> 5;
    int per = (n + 1023) / 1024;
    int base = t * per;
    int s = 0;
    for (int i = 0; i < per; i++) {
        int idx = base + i;
        if (idx < n) s += g_cnt[idx];
    }
    int incl = s;
    #pragma unroll
    for (int off = 1; off < 32; off <<= 1) {
        int y = __shfl_up_sync(0xffffffffu, incl, off);
        if (lane >= off) incl += y;
    }
    if (lane == 31) ws[wd] = incl;
    __syncthreads();
    if (wd == 0) {
        int v = ws[lane];
        int iv = v;
        #pragma unroll
        for (int off = 1; off < 32; off <<= 1) {
            int y = __shfl_up_sync(0xffffffffu, iv, off);
            if (lane >= off) iv += y;
        }
        ws[lane] = iv - v;
    }
    __syncthreads();
    int run = ws[wd] + incl - s;
    for (int i = 0; i < per; i++) {
        int idx = base + i;
        if (idx < n) {
            int v = g_cnt[idx];
            g_cur[idx] = run;
            run += v;
        }
    }
}

__global__ void k_scatter(const void* __restrict__ ei, int E) {
    int e = blockIdx.x * blockDim.x + threadIdx.x;
    if (e < E) {
        int pos = atomicAdd(&g_cur[get_dst(ei, e)], 1);
        g_perm[pos] = e;
    }
}

// ---------------- fused edge kernel ----------------
#define KB_B(p)  ((p) * 32768)
#define VB_B(p)  (65536 + (p) * 32768)
#define DT_B(p)  (131072 + (p) * 256)
#define EXS_B    131584
#define SMEM_E   132608

__device__ __forceinline__ void prefetch64(char* sm, int p, const float* __restrict__ ke,
                                           const float* __restrict__ ve,
                                           const void* __restrict__ ei,
                                           int tile, int E, int tid) {
    int half = tid >> 8;            // 0: k, 1: v
    int r = (tid & 255) >> 2;       // row 0..63
    int q = tid & 3;
    int gi = tile * TILE + r;
    if (gi >= E) gi = E - 1;
    int pe = g_perm[gi];
    const float* src = (half ? ve : ke) + (size_t)pe * DIM + q * 32;
    uint32_t sd = (uint32_t)__cvta_generic_to_shared(
        sm + (half ? VB_B(p) : KB_B(p)) + (r * 128 + q * 32) * 4);
    #pragma unroll
    for (int j = 0; j < 8; j++) cp16(sd + j * 16, (const char*)src + j * 16);
    if (tid < TILE) {
        int gi2 = tile * TILE + tid;
        if (gi2 >= E) gi2 = E - 1;
        ((int*)(sm + DT_B(p)))[tid] = get_dst(ei, g_perm[gi2]);
    }
}

__global__ __launch_bounds__(512, 1) void k_edge(const float* __restrict__ ke,
                                                 const float* __restrict__ ve,
                                                 const void* __restrict__ ei,
                                                 int E, int ntiles) {
    extern __shared__ char sm[];
    float* exs = (float*)(sm + EXS_B);
    int tid = threadIdx.x, lane = tid & 31, w = tid >> 5;
    int STRIDE = gridDim.x, bid = blockIdx.x;

    if (bid < ntiles) prefetch64(sm, 0, ke, ve, ei, bid, E, tid);
    asm volatile("cp.async.commit_group;");

    int par = 0;
    for (int t = bid; t < ntiles; t += STRIDE, par ^= 1) {
        int nt = t + STRIDE;
        if (nt < ntiles) prefetch64(sm, par ^ 1, ke, ve, ei, nt, E, tid);
        asm volatile("cp.async.commit_group;");
        asm volatile("cp.async.wait_group 1;");
        __syncthreads();   // tile t buffers + dt visible

        const float* kb = (const float*)(sm + KB_B(par));
        const int*   dt = (const int*)(sm + DT_B(par));

        // phase A: scores (warp per 4 edges), w-tilde register-cached per dst segment
        {
            int prevd = -1;
            float4 wv0, wv1, wv2, wv3;
            #pragma unroll
            for (int i = 0; i < 4; i++) {
                int e = w * 4 + i;
                int gi = t * TILE + e;
                int d = dt[e];
                if (d != prevd) {
                    const float* base = g_wt + (size_t)d * 512 + lane * 4;
                    wv0 = __ldg((const float4*)(base + 0));
                    wv1 = __ldg((const float4*)(base + 128));
                    wv2 = __ldg((const float4*)(base + 256));
                    wv3 = __ldg((const float4*)(base + 384));
                    prevd = d;
                }
                float4 kv = *(const float4*)&kb[e * 128 + lane * 4];
                float p0 = kv.x * wv0.x + kv.y * wv0.y + kv.z * wv0.z + kv.w * wv0.w;
                float p1 = kv.x * wv1.x + kv.y * wv1.y + kv.z * wv1.z + kv.w * wv1.w;
                float p2 = kv.x * wv2.x + kv.y * wv2.y + kv.z * wv2.z + kv.w * wv2.w;
                float p3 = kv.x * wv3.x + kv.y * wv3.y + kv.z * wv3.z + kv.w * wv3.w;
                #pragma unroll
                for (int off = 16; off >= 1; off >>= 1) {
                    p0 += __shfl_xor_sync(0xffffffffu, p0, off);
                    p1 += __shfl_xor_sync(0xffffffffu, p1, off);
                    p2 += __shfl_xor_sync(0xffffffffu, p2, off);
                    p3 += __shfl_xor_sync(0xffffffffu, p3, off);
                }
                if (lane < 4) {
                    float s = (lane == 0) ? p0 : (lane == 1) ? p1 : (lane == 2) ? p2 : p3;
                    s += __ldg(&g_c[d * 4 + lane]);
                    exs[e * 4 + lane] = (gi < E) ? __expf(s) : 0.f;
                }
            }
        }
        __syncthreads();   // exs ready

        // phase B: weighted aggregation of raw v, segmented by dst
        {
            const float* vb = (const float*)(sm + VB_B(par));
            int h = tid >> 7, c = tid & 127;
            float a = 0.f;
            #pragma unroll 4
            for (int r = 0; r < TILE; r++) {
                a += exs[r * 4 + h] * vb[r * 128 + c];
                if (r == TILE - 1 || dt[r + 1] != dt[r]) {
                    atomicAdd(&g_S[(size_t)dt[r] * 512 + h * 128 + c], a);
                    a = 0.f;
                }
            }
            if (tid < 8) {
                int hh = tid & 3, hf = tid >> 2;
                int r0 = hf * 32, r1 = r0 + 32;
                float aa = 0.f;
                for (int r = r0; r < r1; r++) {
                    aa += exs[r * 4 + hh];
                    if (r == r1 - 1 || dt[r + 1] != dt[r]) {
                        atomicAdd(&g_den[dt[r] * HEADS + hh], aa);
                        aa = 0.f;
                    }
                }
            }
        }
        __syncthreads();   // buffer reads complete before re-prefetch
    }
}

// ---------------- post: agg = (S @ Wv)/den + bv ----------------
__global__ __launch_bounds__(256) void k_vproj(const float* __restrict__ Wv,
                                               const float* __restrict__ bv, int n) {
    extern __shared__ float sv[];
    float* Ws = sv;               // [128][128]
    float* Ss = sv + 128 * 128;   // [32][4][136]
    int tid = threadIdx.x;
    int row0 = blockIdx.x * 32;
    for (int i = tid; i < DIM * DIM; i += 256) Ws[i] = Wv[i];
    for (int i = tid; i < 32 * 512; i += 256) {
        int nl = i >> 9, rest = i & 511;
        int h = rest >> 7, d = rest & 127;
        int gr = row0 + nl;
        Ss[nl * 544 + h * 136 + d] = (gr < n) ? g_S[(size_t)gr * 512 + rest] : 0.f;
    }
    __syncthreads();
    int cg = (tid & 31) * 4, rg = (tid >> 5) * 4;
    int h = cg >> 5;
    float acc[4][4] = {};
    #pragma unroll 8
    for (int d = 0; d < DIM; d++) {
        float4 wv = *(float4*)&Ws[d * DIM + cg];
        float a0 = Ss[(rg + 0) * 544 + h * 136 + d];
        float a1 = Ss[(rg + 1) * 544 + h * 136 + d];
        float a2 = Ss[(rg + 2) * 544 + h * 136 + d];
        float a3 = Ss[(rg + 3) * 544 + h * 136 + d];
        acc[0][0] += a0 * wv.x; acc[0][1] += a0 * wv.y; acc[0][2] += a0 * wv.z; acc[0][3] += a0 * wv.w;
        acc[1][0] += a1 * wv.x; acc[1][1] += a1 * wv.y; acc[1][2] += a1 * wv.z; acc[1][3] += a1 * wv.w;
        acc[2][0] += a2 * wv.x; acc[2][1] += a2 * wv.y; acc[2][2] += a2 * wv.z; acc[2][3] += a2 * wv.w;
        acc[3][0] += a3 * wv.x; acc[3][1] += a3 * wv.y; acc[3][2] += a3 * wv.z; acc[3][3] += a3 * wv.w;
    }
    float4 bb = *(const float4*)&bv[cg];
    #pragma unroll
    for (int rr = 0; rr < 4; rr++) {
        int gr = row0 + rg + rr;
        if (gr < n) {
            float den = g_den[gr * HEADS + h];
            float4 o;
            if (den > 0.f) {
                float inv = 1.f / den;
                o = make_float4(acc[rr][0] * inv + bb.x, acc[rr][1] * inv + bb.y,
                                acc[rr][2] * inv + bb.z, acc[rr][3] * inv + bb.w);
            } else {
                o = make_float4(0.f, 0.f, 0.f, 0.f);
            }
            *(float4*)&g_agg[gr * DIM + cg] = o;
        }
    }
}

// ---------------- out = agg @ Wo + bo ----------------
__global__ __launch_bounds__(256) void k_out(const float* __restrict__ W,
                                             const float* __restrict__ b,
                                             float* __restrict__ Y, int n) {
    extern __shared__ float so[];
    float* Ws = so;
    float* As = so + DIM * DIM;
    int tid = threadIdx.x;
    for (int i = tid; i < DIM * DIM; i += 256) Ws[i] = W[i];
    int row0 = blockIdx.x * 32;
    for (int i = tid; i < 32 * DIM; i += 256) {
        int r = i >> 7, c = i & 127;
        int gr = row0 + r;
        As[r * 132 + c] = (gr < n) ? g_agg[gr * DIM + c] : 0.f;
    }
    __syncthreads();
    int cg = (tid & 31) * 4, rg = (tid >> 5) * 4;
    float acc[4][4] = {};
    #pragma unroll 8
    for (int d = 0; d < DIM; d++) {
        float4 w = *(float4*)&Ws[d * DIM + cg];
        float a0 = As[(rg + 0) * 132 + d];
        float a1 = As[(rg + 1) * 132 + d];
        float a2 = As[(rg + 2) * 132 + d];
        float a3 = As[(rg + 3) * 132 + d];
        acc[0][0] += a0 * w.x; acc[0][1] += a0 * w.y; acc[0][2] += a0 * w.z; acc[0][3] += a0 * w.w;
        acc[1][0] += a1 * w.x; acc[1][1] += a1 * w.y; acc[1][2] += a1 * w.z; acc[1][3] += a1 * w.w;
        acc[2][0] += a2 * w.x; acc[2][1] += a2 * w.y; acc[2][2] += a2 * w.z; acc[2][3] += a2 * w.w;
        acc[3][0] += a3 * w.x; acc[3][1] += a3 * w.y; acc[3][2] += a3 * w.z; acc[3][3] += a3 * w.w;
    }
    float4 bb = *(const float4*)&b[cg];
    #pragma unroll
    for (int rr = 0; rr < 4; rr++) {
        int gr = row0 + rg + rr;
        if (gr < n) {
            float4 o = make_float4(acc[rr][0] + bb.x, acc[rr][1] + bb.y,
                                   acc[rr][2] + bb.z, acc[rr][3] + bb.w);
            *(float4*)&Y[gr * DIM + cg] = o;
        }
    }
}

extern "C" void kernel_launch(void* const* d_in, const int* in_sizes, int n_in,
                              void* d_out, int out_size) {
    const float* q_nodes = (const float*)d_in[0];
    const float* k_edges = (const float*)d_in[1];
    const float* v_edges = (const float*)d_in[2];
    const float* Wq = (const float*)d_in[3];
    const float* bq = (const float*)d_in[4];
    const float* Wk = (const float*)d_in[5];
    const float* bk = (const float*)d_in[6];
    const float* Wv = (const float*)d_in[7];
    const float* bv = (const float*)d_in[8];
    const float* Wo = (const float*)d_in[9];
    const float* bo = (const float*)d_in[10];
    const void*  ei = (const void*)d_in[11];

    int N = in_sizes[0] / DIM;
    int E = in_sizes[1] / DIM;
    int ntiles = (E + TILE - 1) / TILE;

    int dev = 0, sms = 148;
    cudaGetDevice(&dev);
    cudaDeviceGetAttribute(&sms, cudaDevAttrMultiProcessorCount, dev);

    const int smem_qw = (128 * 132 + 32 * 132 + 32 * 132) * (int)sizeof(float);
    const int smem_vp = (128 * 128 + 32 * 544) * (int)sizeof(float);
    const int smem_sm = (DIM * DIM + 32 * 132) * (int)sizeof(float);
    cudaFuncSetAttribute(k_qw, cudaFuncAttributeMaxDynamicSharedMemorySize, smem_qw);
    cudaFuncSetAttribute(k_vproj, cudaFuncAttributeMaxDynamicSharedMemorySize, smem_vp);
    cudaFuncSetAttribute(k_out, cudaFuncAttributeMaxDynamicSharedMemorySize, smem_sm);
    cudaFuncSetAttribute(k_edge, cudaFuncAttributeMaxDynamicSharedMemorySize, SMEM_E);

    k_zero_detect<<<256, 256>>>(ei, E);
    k_qw<<<(N + 31) / 32, 256, smem_qw>>>(q_nodes, Wq, bq, Wk, bk, N);
    k_hist<<<(E + 255) / 256, 256>>>(ei, E);
    k_scan<<<1, 1024>>>(N);
    k_scatter<<<(E + 255) / 256, 256>>>(ei, E);
    k_edge<<<sms, 512, SMEM_E>>>(k_edges, v_edges, ei, E, ntiles);
    k_vproj<<<(N + 31) / 32, 256, smem_vp>>>(Wv, bv, N);
    k_out<<<(N + 31) / 32, 256, smem_sm>>>(Wo, bo, (float*)d_out, N);
}